// round 4
// baseline (speedup 1.0000x reference)
#include <cuda_runtime.h>
#include <cuda_bf16.h>

// Inverse db1 DWT (Haar reconstruction), grouped transposed conv 2x2 stride 2.
// x: (B=16, C=128, H=128, W=128) f32; inv_filters: (2,2,2) f32
// out: (B=16, G=64, 2H=256, 2W=256) f32
//
// out[b,g,2h+i,2w+j] = x[b,2g,h,w]*f0[i,j] + x[b,2g+1,h,w]*f1[i,j]
//
// One thread: 2 input pixels along w (float2 from lo + float2 from hi chan),
// writes 2 float4 rows of the 2x4 output patch. All accesses coalesced.

static constexpr int B  = 16;
static constexpr int C  = 128;
static constexpr int G  = 64;   // C/2 groups
static constexpr int H  = 128;
static constexpr int W  = 128;
static constexpr int W2 = W / 2;             // pixels-pairs per row = 64
static constexpr long long TOTAL = (long long)B * G * H * W2;  // 8,388,608 threads

__global__ __launch_bounds__(256)
void iwt_kernel(const float* __restrict__ x,
                const float* __restrict__ f,
                float* __restrict__ out)
{
    int idx = blockIdx.x * blockDim.x + threadIdx.x;   // < 2^23, fits int
    // decompose: idx = ((bg * H) + h) * W2 + w2
    int w2 = idx & (W2 - 1);           // 0..63
    int h  = (idx >> 6) & (H - 1);     // 0..127
    int bg = idx >> 13;                // b*G + g, 0..1023

    // input: channel pair (2*bg, 2*bg+1); plane = H*W = 16384
    long long lo_off = (long long)(2 * bg) * (H * W) + h * W + 2 * w2;
    float2 lo = *reinterpret_cast<const float2*>(x + lo_off);
    float2 hi = *reinterpret_cast<const float2*>(x + lo_off + H * W);

    // filters: f[0..3] = f0[i*2+j], f[4..7] = f1[i*2+j]
    float f00 = __ldg(f + 0), f01 = __ldg(f + 1);
    float f02 = __ldg(f + 2), f03 = __ldg(f + 3);
    float g00 = __ldg(f + 4), g01 = __ldg(f + 5);
    float g02 = __ldg(f + 6), g03 = __ldg(f + 7);

    // output: plane per (b,g) = 256*256 = 65536; rows 2h and 2h+1, cols 4*w2..4*w2+3
    long long o_off = (long long)bg * (2 * H * 2 * W) + (2 * h) * (2 * W) + 4 * w2;

    float4 r0, r1;
    r0.x = fmaf(hi.x, g00, lo.x * f00);
    r0.y = fmaf(hi.x, g01, lo.x * f01);
    r0.z = fmaf(hi.y, g00, lo.y * f00);
    r0.w = fmaf(hi.y, g01, lo.y * f01);

    r1.x = fmaf(hi.x, g02, lo.x * f02);
    r1.y = fmaf(hi.x, g03, lo.x * f03);
    r1.z = fmaf(hi.y, g02, lo.y * f02);
    r1.w = fmaf(hi.y, g03, lo.y * f03);

    *reinterpret_cast<float4*>(out + o_off)           = r0;
    *reinterpret_cast<float4*>(out + o_off + 2 * W)   = r1;
}

extern "C" void kernel_launch(void* const* d_in, const int* in_sizes, int n_in,
                              void* d_out, int out_size)
{
    const float* x = (const float*)d_in[0];
    const float* f = (const float*)d_in[1];
    float* out     = (float*)d_out;

    const int threads = 256;
    const int blocks  = (int)(TOTAL / threads);   // 32768, exact
    iwt_kernel<<<blocks, threads>>>(x, f, out);
}